// round 17
// baseline (speedup 1.0000x reference)
#include <cuda_runtime.h>

// GraphSAGE on GB300 — 5 kernels (layer1 at launch #4 for ncu):
//   K1 hist:  rank[e] = cnt[dst]++ (atomic returns stored!); block0 folds
//             W2l@Wc/W2r@Wc/bc2 AND packs [W1l;W1r] tf32 B-frags (g_Wfrag)
//   K2 scan:  single-pass exclusive scan (decoupled lookback)
//   K3 fill:  csr[off[dst] + rank[e]] = src   — NO atomics
//   K4 layer1 FUSED: warp-cooperative gather (16 lanes/node, csr batch-load
//             + width-16 half-warp shuffles; full batches unguarded) into an
//             [m][k] tf32 smem tile, then mma.sync.m16n8k8.tf32, folded
//             layer2+classifier epilogue.
//   K5 final: out[i] = mean_{e:dst=i} t[src[e]] + r[i] + bc2; reset state

#define NMAX 100000
#define EMAX 1600000
#define NB_SCAN ((NMAX + 1023) / 1024)   // 98
#define S_STRIDE 132                      // 128 k + 4 pad (conflict-free frags)

__device__ float2 g_t[NMAX];
__device__ float2 g_r[NMAX];
__device__ int    g_cnt[NMAX];           // zero-init; re-zeroed by K5
__device__ int    g_off[NMAX + 1];
__device__ int    g_rank[EMAX];          // edge's rank within its dst bucket
__device__ int    g_csr[EMAX];
__device__ int    g_bsum[NB_SCAN];
__device__ volatile int g_bflag[NB_SCAN]; // zero-init; re-zeroed by K5
__device__ float2 g_Wfrag[16 * 8 * 32];   // [kstep][ntile][lane] tf32 B frags
__device__ float  g_W2lc[128];
__device__ float  g_W2rc[128];
__device__ float  g_bc2[2];

__device__ __forceinline__ int edge_val(const int* __restrict__ w, int is64, int idx) {
    return is64 ? w[2 * idx] : w[idx];   // int64 little-endian low word, or int32
}
__device__ __forceinline__ int sniff64(const int* __restrict__ w) {
    int odd = 0;
#pragma unroll
    for (int j = 1; j < 64; j += 2) odd |= w[j];
    return odd == 0;
}
__device__ __forceinline__ unsigned tf32r(float f) {
    unsigned u;
    asm("cvt.rna.tf32.f32 %0, %1;" : "=r"(u) : "f"(f));
    return u;
}
__device__ __forceinline__ void mma_tf32(float* c, unsigned a0, unsigned a1,
                                         unsigned a2, unsigned a3,
                                         unsigned b0, unsigned b1) {
    asm("mma.sync.aligned.m16n8k8.row.col.f32.tf32.tf32.f32 "
        "{%0,%1,%2,%3}, {%4,%5,%6,%7}, {%8,%9}, {%0,%1,%2,%3};"
        : "+f"(c[0]), "+f"(c[1]), "+f"(c[2]), "+f"(c[3])
        : "r"(a0), "r"(a1), "r"(a2), "r"(a3), "r"(b0), "r"(b1));
}

// ---------------------------------------------------------------- K1: hist(+rank) + fold + Wfrag pack
__global__ void sage_hist_kernel(const int* __restrict__ ei, int E, int nn,
                                 const float* __restrict__ W1l,
                                 const float* __restrict__ W1r,
                                 const float* __restrict__ W2l,
                                 const float* __restrict__ b2,
                                 const float* __restrict__ W2r,
                                 const float* __restrict__ Wc,
                                 const float* __restrict__ bc) {
    __shared__ int s_is64;
    int t = threadIdx.x;
    if (t == 0) s_is64 = sniff64(ei);
    __syncthreads();
    int is64 = s_is64;

    if (blockIdx.x == 0) {
        if (t < 128) {                   // fold W2l@Wc, W2r@Wc
            int k = t >> 1, c = t & 1;
            float s = 0.f, sr = 0.f;
#pragma unroll
            for (int m = 0; m < 64; m++) {
                float w = Wc[m * 2 + c];
                s  += W2l[k * 64 + m] * w;
                sr += W2r[k * 64 + m] * w;
            }
            g_W2lc[k * 2 + c] = s;
            g_W2rc[k * 2 + c] = sr;
        }
        if (t < 2) {
            float sb = 0.f;
            for (int m = 0; m < 64; m++) sb += b2[m] * Wc[m * 2 + t];
            g_bc2[t] = sb + bc[t];
        }
        // pack B fragments: B[k][n] = k<64 ? W1l[k][n] : W1r[k-64][n]
        // frag (kstep s, ntile nt, lane l): {B[s*8+tg][nt*8+gr], B[s*8+tg+4][nt*8+gr]}
#pragma unroll
        for (int q = 0; q < 16; q++) {
            int idx = t * 16 + q;                 // 0..4095
            int lane = idx & 31;
            int nt   = (idx >> 5) & 7;
            int s    = idx >> 8;
            int gr = lane >> 2, tg = lane & 3;
            int k0 = s * 8 + tg, k1 = k0 + 4;
            int n  = nt * 8 + gr;
            float v0 = (k0 < 64) ? W1l[k0 * 64 + n] : W1r[(k0 - 64) * 64 + n];
            float v1 = (k1 < 64) ? W1l[k1 * 64 + n] : W1r[(k1 - 64) * 64 + n];
            float2 o;
            o.x = __uint_as_float(tf32r(v0));
            o.y = __uint_as_float(tf32r(v1));
            g_Wfrag[idx] = o;
        }
    }

    int base = (blockIdx.x * blockDim.x + t) * 4;
#pragma unroll
    for (int u = 0; u < 4; u++) {
        int e = base + u;
        if (e < E) {
            int dst = edge_val(ei, is64, E + e);
            if ((unsigned)dst < (unsigned)nn)
                g_rank[e] = atomicAdd(&g_cnt[dst], 1);   // keep the rank!
        }
    }
}

// ---------------------------------------------------------------- K2: single-pass scan
__global__ void sage_scan_kernel(int n, int nb) {
    __shared__ int wsum[32];
    __shared__ int pre_s;
    int b = blockIdx.x;
    int t = threadIdx.x;
    int lane = t & 31, wid = t >> 5;
    int i = b * 1024 + t;
    int v = (i < n) ? g_cnt[i] : 0;
    int x = v;
#pragma unroll
    for (int d = 1; d < 32; d <<= 1) {
        int y = __shfl_up_sync(0xffffffffu, x, d);
        if (lane >= d) x += y;
    }
    if (lane == 31) wsum[wid] = x;
    __syncthreads();
    if (wid == 0) {
        int w = wsum[lane];
        int xw = w;
#pragma unroll
        for (int d = 1; d < 32; d <<= 1) {
            int y = __shfl_up_sync(0xffffffffu, xw, d);
            if (lane >= d) xw += y;
        }
        wsum[lane] = xw;
    }
    __syncthreads();
    int total = wsum[31];
    if (t == 0) {
        pre_s = 0;
        g_bsum[b] = total;
        __threadfence();
        g_bflag[b] = 1;
    }
    __syncthreads();
    if (t < b) {
        while (g_bflag[t] == 0) {}
        __threadfence();
        atomicAdd(&pre_s, g_bsum[t]);
    }
    __syncthreads();
    int pre = pre_s;
    int wexcl = (wid == 0) ? 0 : wsum[wid - 1];
    if (i < n) g_off[i] = pre + (x - v) + wexcl;
    if (b == nb - 1 && t == 0) g_off[n] = pre + total;
}

// ---------------------------------------------------------------- K3: fill (no atomics)
__global__ void sage_fill_kernel(const int* __restrict__ ei, int E, int nn) {
    __shared__ int s_is64;
    if (threadIdx.x == 0) s_is64 = sniff64(ei);
    __syncthreads();
    int is64 = s_is64;
    int base = (blockIdx.x * blockDim.x + threadIdx.x) * 4;
#pragma unroll
    for (int u = 0; u < 4; u++) {
        int e = base + u;
        if (e < E) {
            int src = edge_val(ei, is64, e);
            int dst = edge_val(ei, is64, E + e);
            if ((unsigned)dst < (unsigned)nn && (unsigned)src < (unsigned)nn) {
                int p = g_off[dst] + g_rank[e];
                if ((unsigned)p < (unsigned)EMAX)
                    g_csr[p] = src;
            }
        }
    }
}

// ---------------------------------------------------------------- K4: fused gather + tf32 MMA + epilogue
// Gather: 16 lanes per node; per 16-edge batch lane c loads csr[e0+c]
// (coalesced 64B) and width-16 half-warp shuffles broadcast each index ->
// 16 INDEPENDENT x loads per batch (MLP=16). FULL batches run unguarded
// (no s>=0 predicate); only the final partial batch carries guards.
// tf32-rounded into S[m][k] (A|X concat k=128). GEMM: mma.m16n8k8.tf32,
// 8 warps (4 m-tiles x 2 n-halves); epilogue folds layer2+classifier.
__global__ void __launch_bounds__(256, 5) sage_layer1_kernel(
        const float* __restrict__ x,
        const float* __restrict__ b1,
        int nn) {
    __shared__ unsigned S_u[64 * S_STRIDE];   // tf32 bits, [m][k] + pad
    __shared__ float4 part[2][64];            // per-n-half partial (t0,t1,r0,r1)
    __shared__ float b1_s[64];
    __shared__ float Wlc_s[128];
    __shared__ float Wrc_s[128];

    int tid = threadIdx.x;
    if (tid < 64)  b1_s[tid] = b1[tid];
    if (tid >= 64 && tid < 192) {
        Wlc_s[tid - 64] = g_W2lc[tid - 64];
        Wrc_s[tid - 64] = g_W2rc[tid - 64];
    }

    int m0 = blockIdx.x * 64;
    {   // ---- gather phase: 4 passes x 16 nodes, 16 lanes per node
        int c  = tid & 15;          // float4 chunk; also lane-in-group
        int pn = tid >> 4;          // 0..15
        unsigned gmask = 0xFFFFu << (tid & 16);   // THIS half-warp only
#pragma unroll 1
        for (int p = 0; p < 4; p++) {
            int m  = p * 16 + pn;
            int gm = m0 + m;
            float4 acc = make_float4(0.f, 0.f, 0.f, 0.f);
            float4 xr  = make_float4(0.f, 0.f, 0.f, 0.f);
            if (gm < nn) {                       // group-uniform guard
                xr = __ldg((const float4*)(x + (size_t)gm * 64) + c);
                int s0 = g_off[gm], s1 = g_off[gm + 1];
                int e0 = s0;
                for (; e0 + 16 <= s1; e0 += 16) {        // FULL batches: no guards
                    int idx = g_csr[e0 + c];             // coalesced 64B batch
#pragma unroll
                    for (int j = 0; j < 16; j++) {
                        int s = __shfl_sync(gmask, idx, j, 16);
                        float4 v = __ldg((const float4*)(x + (size_t)s * 64) + c);
                        acc.x += v.x; acc.y += v.y;
                        acc.z += v.z; acc.w += v.w;
                    }
                }
                if (e0 < s1) {                           // partial batch: guarded
                    int my = e0 + c;
                    int idx = (my < s1) ? g_csr[my] : -1;
#pragma unroll
                    for (int j = 0; j < 16; j++) {
                        int s = __shfl_sync(gmask, idx, j, 16);
                        if (s >= 0) {
                            float4 v = __ldg((const float4*)(x + (size_t)s * 64) + c);
                            acc.x += v.x; acc.y += v.y;
                            acc.z += v.z; acc.w += v.w;
                        }
                    }
                }
                float inv = 1.0f / fmaxf((float)(s1 - s0), 1.0f);
                acc.x *= inv; acc.y *= inv; acc.z *= inv; acc.w *= inv;
            }
            uint4 ua, ux;
            ua.x = tf32r(acc.x); ua.y = tf32r(acc.y);
            ua.z = tf32r(acc.z); ua.w = tf32r(acc.w);
            ux.x = tf32r(xr.x);  ux.y = tf32r(xr.y);
            ux.z = tf32r(xr.z);  ux.w = tf32r(xr.w);
            *(uint4*)&S_u[m * S_STRIDE + c * 4]      = ua;   // A part: k 0..63
            *(uint4*)&S_u[m * S_STRIDE + 64 + c * 4] = ux;   // X part: k 64..127
        }
    }
    __syncthreads();

    // ---- MMA phase
    int lane = tid & 31;
    int w    = tid >> 5;
    int mt   = w & 3;            // m-tile (16 rows)
    int nh   = w >> 2;           // n-half (32 cols)
    int gr = lane >> 2, tg = lane & 3;

    float acc[4][4];
#pragma unroll
    for (int j = 0; j < 4; j++)
#pragma unroll
        for (int q = 0; q < 4; q++) acc[j][q] = 0.f;

    const float2* __restrict__ wf = g_Wfrag;
    int rowA = (mt * 16 + gr) * S_STRIDE;
#pragma unroll 4
    for (int s = 0; s < 16; s++) {
        int ka = s * 8 + tg;
        unsigned a0 = S_u[rowA + ka];
        unsigned a1 = S_u[rowA + 8 * S_STRIDE + ka];
        unsigned a2 = S_u[rowA + ka + 4];
        unsigned a3 = S_u[rowA + 8 * S_STRIDE + ka + 4];
#pragma unroll
        for (int j = 0; j < 4; j++) {
            int nt = nh * 4 + j;
            float2 b = __ldg(&wf[(s * 8 + nt) * 32 + lane]);
            mma_tf32(acc[j], a0, a1, a2, a3,
                     __float_as_uint(b.x), __float_as_uint(b.y));
        }
    }

    // ---- epilogue: relu + fold layer2/classifier over this warp's 32 cols
    float tA0 = 0.f, tA1 = 0.f, rA0 = 0.f, rA1 = 0.f;   // row gr
    float tB0 = 0.f, tB1 = 0.f, rB0 = 0.f, rB1 = 0.f;   // row gr+8
#pragma unroll
    for (int j = 0; j < 4; j++) {
        int c0 = nh * 32 + j * 8 + 2 * tg;
        int c1 = c0 + 1;
        float h00 = fmaxf(acc[j][0] + b1_s[c0], 0.f);
        float h01 = fmaxf(acc[j][1] + b1_s[c1], 0.f);
        float h10 = fmaxf(acc[j][2] + b1_s[c0], 0.f);
        float h11 = fmaxf(acc[j][3] + b1_s[c1], 0.f);
        tA0 += h00 * Wlc_s[c0 * 2 + 0] + h01 * Wlc_s[c1 * 2 + 0];
        tA1 += h00 * Wlc_s[c0 * 2 + 1] + h01 * Wlc_s[c1 * 2 + 1];
        rA0 += h00 * Wrc_s[c0 * 2 + 0] + h01 * Wrc_s[c1 * 2 + 0];
        rA1 += h00 * Wrc_s[c0 * 2 + 1] + h01 * Wrc_s[c1 * 2 + 1];
        tB0 += h10 * Wlc_s[c0 * 2 + 0] + h11 * Wlc_s[c1 * 2 + 0];
        tB1 += h10 * Wlc_s[c0 * 2 + 1] + h11 * Wlc_s[c1 * 2 + 1];
        rB0 += h10 * Wrc_s[c0 * 2 + 0] + h11 * Wrc_s[c1 * 2 + 0];
        rB1 += h10 * Wrc_s[c0 * 2 + 1] + h11 * Wrc_s[c1 * 2 + 1];
    }
#pragma unroll
    for (int d = 1; d <= 2; d <<= 1) {   // reduce across the 4 tg lanes
        tA0 += __shfl_xor_sync(0xffffffffu, tA0, d);
        tA1 += __shfl_xor_sync(0xffffffffu, tA1, d);
        rA0 += __shfl_xor_sync(0xffffffffu, rA0, d);
        rA1 += __shfl_xor_sync(0xffffffffu, rA1, d);
        tB0 += __shfl_xor_sync(0xffffffffu, tB0, d);
        tB1 += __shfl_xor_sync(0xffffffffu, tB1, d);
        rB0 += __shfl_xor_sync(0xffffffffu, rB0, d);
        rB1 += __shfl_xor_sync(0xffffffffu, rB1, d);
    }
    if (tg == 0) {
        part[nh][mt * 16 + gr]     = make_float4(tA0, tA1, rA0, rA1);
        part[nh][mt * 16 + gr + 8] = make_float4(tB0, tB1, rB0, rB1);
    }
    __syncthreads();

    if (tid < 64) {
        float4 u = part[0][tid];
        float4 v = part[1][tid];
        int gm = m0 + tid;
        if (gm < nn) {
            g_t[gm] = make_float2(u.x + v.x, u.y + v.y);
            g_r[gm] = make_float2(u.z + v.z, u.w + v.w);
        }
    }
}

// ---------------------------------------------------------------- K5: final (+ state reset)
__global__ void sage_final_kernel(float2* __restrict__ out, int nn) {
    int i = blockIdx.x * blockDim.x + threadIdx.x;
    if (blockIdx.x == 0 && threadIdx.x < NB_SCAN) g_bflag[threadIdx.x] = 0;
    if (i >= nn) return;
    g_cnt[i] = 0;                            // restore for next replay
    int s0 = g_off[i], s1 = g_off[i + 1];
    float a0 = 0.f, a1 = 0.f, b0 = 0.f, b1v = 0.f;
    int e = s0;
    for (; e + 1 < s1; e += 2) {
        float2 vA = g_t[g_csr[e]];
        float2 vB = g_t[g_csr[e + 1]];
        a0 += vA.x; a1 += vA.y;
        b0 += vB.x; b1v += vB.y;
    }
    if (e < s1) {
        float2 vA = g_t[g_csr[e]];
        a0 += vA.x; a1 += vA.y;
    }
    float inv = 1.0f / fmaxf((float)(s1 - s0), 1.0f);
    float2 rv = g_r[i];
    out[i] = make_float2((a0 + b0) * inv + rv.x + g_bc2[0],
                         (a1 + b1v) * inv + rv.y + g_bc2[1]);
}

// ---------------------------------------------------------------- launch
extern "C" void kernel_launch(void* const* d_in, const int* in_sizes, int n_in,
                              void* d_out, int out_size) {
    const float* x   = (const float*)d_in[0];
    const int*   ei  = (const int*)d_in[1];     // int32 or int64 (auto-detected)
    const float* W1l = (const float*)d_in[2];
    const float* b1  = (const float*)d_in[3];
    const float* W1r = (const float*)d_in[4];
    const float* W2l = (const float*)d_in[5];
    const float* b2  = (const float*)d_in[6];
    const float* W2r = (const float*)d_in[7];
    const float* Wc  = (const float*)d_in[8];
    const float* bc  = (const float*)d_in[9];

    int nn = in_sizes[0] / 64;
    int E  = in_sizes[1] / 2;
    if (nn > NMAX) nn = NMAX;
    if (E > EMAX)  E = EMAX;
    int nb = (nn + 1023) / 1024;

    sage_hist_kernel<<<(E / 4 + 255) / 256, 256>>>(ei, E, nn, W1l, W1r,
                                                   W2l, b2, W2r, Wc, bc);
    sage_scan_kernel<<<nb, 1024>>>(nn, nb);
    sage_fill_kernel<<<(E / 4 + 255) / 256, 256>>>(ei, E, nn);
    sage_layer1_kernel<<<(nn + 63) / 64, 256>>>(x, b1, nn);             // launch #4
    sage_final_kernel<<<(nn + 255) / 256, 256>>>((float2*)d_out, nn);
}